// round 10
// baseline (speedup 1.0000x reference)
#include <cuda_runtime.h>

// RandFlow: depthwise 41x41 Gaussian (sigma=5) of flow = 2*noise-1, separable.
// R10 = R9 + pass2 reshaped: 8 out/thread, ring W=16, 8 blocks/SM (occ ~50%)
// to hide the LDG prologue behind resident warps. FFMA2 everywhere.

#define IMG_H 512
#define IMG_W 512
#define IMG_B 16

__device__ unsigned long long g_scratch[IMG_B * IMG_H * IMG_W]; // float2 as u64

__device__ constexpr float GK[41] = {
    0.00033546f, 0.00073182f, 0.00153381f, 0.00308872f, 0.00597603f,
    0.01110900f, 0.01984110f, 0.03404746f, 0.05613476f, 0.08892166f,
    0.13533528f, 0.19789871f, 0.27803730f, 0.37531110f, 0.48675226f,
    0.60653066f, 0.72614904f, 0.83527021f, 0.92311635f, 0.98019867f,
    1.00000000f,
    0.98019867f, 0.92311635f, 0.83527021f, 0.72614904f, 0.60653066f,
    0.48675226f, 0.37531110f, 0.27803730f, 0.19789871f, 0.13533528f,
    0.08892166f, 0.05613476f, 0.03404746f, 0.01984110f, 0.01110900f,
    0.00597603f, 0.00308872f, 0.00153381f, 0.00073182f, 0.00033546f
};

// fold 1/S^2 (S = 12.5326388) and (2x-1) into pass-1 load
#define SCALE_A 0.012733434f
#define SCALE_B (-0.006366717f)

__device__ __forceinline__ unsigned long long pk2(float g) {
    unsigned int u = __float_as_uint(g);   // constant-folds for literals
    return ((unsigned long long)u << 32) | (unsigned long long)u;
}
__device__ __forceinline__ void ffma2(unsigned long long& d,
                                      unsigned long long a,
                                      unsigned long long b) {
    asm("fma.rn.f32x2 %0, %1, %2, %0;" : "+l"(d) : "l"(a), "l"(b));
}

// skew: f(x) = x + (x>>3)
#define SKB 624   // f(551)=619, padded

// ---------------- Pass 1: horizontal, 8 out/thread, ring W1=12 -------------
// 256 threads = 4 rows x 64 threads. Grid = 16*512/4 = 2048.
#define W1 12
__global__ void __launch_bounds__(256) rf_pass1(const float2* __restrict__ in) {
    __shared__ unsigned long long s[4][SKB];
    const int sub  = threadIdx.x >> 6;         // row within block (0..3)
    const int t    = threadIdx.x & 63;         // thread within row
    const int row  = blockIdx.x * 4 + sub;     // b*512 + h
    const float2* src = in + (size_t)row * IMG_W;
    unsigned long long* S = s[sub];

    // interior fill: x = 20 + t + 64j -> w = t + 64j in [0,512), no predicate
    {
        float2 v[8];
#pragma unroll
        for (int j = 0; j < 8; ++j) v[j] = src[t + 64 * j];   // MLP = 8
#pragma unroll
        for (int j = 0; j < 8; ++j) {
            const int x = 20 + t + 64 * j;
            float vx = fmaf(v[j].x, SCALE_A, SCALE_B);
            float vy = fmaf(v[j].y, SCALE_A, SCALE_B);
            *reinterpret_cast<float2*>(&S[x + (x >> 3)]) = make_float2(vx, vy);
        }
        if (t < 20) {                          // zero edges
            S[t + (t >> 3)] = 0ull;
            const int x = 532 + t;
            S[x + (x >> 3)] = 0ull;
        }
    }
    __syncthreads();

    const int base = t * 9;                    // skewed base (w0 = 8t)
    unsigned long long win[W1], acc[8];
#pragma unroll
    for (int i = 0; i < W1; ++i) win[i] = S[base + i + (i >> 3)];
#pragma unroll
    for (int r = 0; r < 8; ++r) acc[r] = 0ull;

#pragma unroll
    for (int k = 0; k < 41; ++k) {
        const unsigned long long g = pk2(GK[k]);
#pragma unroll
        for (int r = 0; r < 8; ++r) ffma2(acc[r], win[(k + r) % W1], g);
        if (k < 37) {                          // prefetch i = k + 12 (max 48)
            const int i = k + W1;
            win[k % W1] = S[base + i + (i >> 3)];
        }
    }
    __syncthreads();

#pragma unroll
    for (int r = 0; r < 8; ++r) S[base + r] = acc[r];
    __syncthreads();

    unsigned long long* dst = g_scratch + (size_t)row * IMG_W;
#pragma unroll
    for (int j = 0; j < 8; ++j) {
        const int x = t + 64 * j;
        dst[x] = S[x + (x >> 3)];
    }
}

// ---------------- Pass 2: vertical, 8 out/thread, ring W2=16 ---------------
// 128 thr = 128 consecutive w; grid = 16*(512/8)*4 = 4096; 8 blocks/SM.
#define W2 16
__global__ void __launch_bounds__(128, 8) rf_pass2(float2* __restrict__ out) {
    const int w  = (blockIdx.x & 3) * 128 + threadIdx.x;
    const int bh = blockIdx.x >> 2;
    const int b  = bh >> 6;                    // 64 h-blocks per batch
    const int h0 = (bh & 63) * 8;

    const unsigned long long* src =
        g_scratch + (size_t)b * IMG_H * IMG_W + w;

    unsigned long long win[W2], acc[8];
#pragma unroll
    for (int i = 0; i < W2; ++i) {
        const int h = h0 + i - 20;
        win[i] = ((unsigned)h < (unsigned)IMG_H) ? src[(size_t)h * IMG_W] : 0ull;
    }
#pragma unroll
    for (int r = 0; r < 8; ++r) acc[r] = 0ull;

#pragma unroll
    for (int k = 0; k < 41; ++k) {
        const unsigned long long g = pk2(GK[k]);
#pragma unroll
        for (int r = 0; r < 8; ++r) ffma2(acc[r], win[(k + r) % W2], g);
        if (k < 32) {                          // prefetch row h0 + k - 4
            const int h = h0 + k - 4;          // = h0 + (k+16) - 20
            win[k % W2] = ((unsigned)h < (unsigned)IMG_H) ? src[(size_t)h * IMG_W]
                                                          : 0ull;
        }
    }

    unsigned long long* dst = (unsigned long long*)out
                            + ((size_t)b * IMG_H + h0) * IMG_W + w;
#pragma unroll
    for (int r = 0; r < 8; ++r) dst[(size_t)r * IMG_W] = acc[r];
}

extern "C" void kernel_launch(void* const* d_in, const int* in_sizes, int n_in,
                              void* d_out, int out_size) {
    const float2* noise = nullptr;
    for (int i = 0; i < n_in; ++i) {
        if (in_sizes[i] == IMG_B * IMG_H * IMG_W * 2) {
            noise = (const float2*)d_in[i];
            break;
        }
    }
    if (!noise) noise = (const float2*)d_in[n_in - 1];

    rf_pass1<<<IMG_B * IMG_H / 4, 256>>>(noise);
    rf_pass2<<<IMG_B * (IMG_H / 8) * (IMG_W / 128), 128>>>((float2*)d_out);
}

// round 11
// speedup vs baseline: 1.1241x; 1.1241x over previous
#include <cuda_runtime.h>

// RandFlow: depthwise 41x41 Gaussian (sigma=5) of flow = 2*noise-1, separable.
// R11: pass1 reworked to 1 warp/row, 16 out/thread (warp-private row ->
// syncwarp only; aux:FFMA2 ratio now matches pass2). Pass2 = R9 (best known).

#define IMG_H 512
#define IMG_W 512
#define IMG_B 16

__device__ unsigned long long g_scratch[IMG_B * IMG_H * IMG_W]; // float2 as u64

__device__ constexpr float GK[41] = {
    0.00033546f, 0.00073182f, 0.00153381f, 0.00308872f, 0.00597603f,
    0.01110900f, 0.01984110f, 0.03404746f, 0.05613476f, 0.08892166f,
    0.13533528f, 0.19789871f, 0.27803730f, 0.37531110f, 0.48675226f,
    0.60653066f, 0.72614904f, 0.83527021f, 0.92311635f, 0.98019867f,
    1.00000000f,
    0.98019867f, 0.92311635f, 0.83527021f, 0.72614904f, 0.60653066f,
    0.48675226f, 0.37531110f, 0.27803730f, 0.19789871f, 0.13533528f,
    0.08892166f, 0.05613476f, 0.03404746f, 0.01984110f, 0.01110900f,
    0.00597603f, 0.00308872f, 0.00153381f, 0.00073182f, 0.00033546f
};

// fold 1/S^2 (S = 12.5326388) and (2x-1) into pass-1 load
#define SCALE_A 0.012733434f
#define SCALE_B (-0.006366717f)

__device__ __forceinline__ unsigned long long pk2(float g) {
    unsigned int u = __float_as_uint(g);   // constant-folds for literals
    return ((unsigned long long)u << 32) | (unsigned long long)u;
}
__device__ __forceinline__ void ffma2(unsigned long long& d,
                                      unsigned long long a,
                                      unsigned long long b) {
    asm("fma.rn.f32x2 %0, %1, %2, %0;" : "+l"(d) : "l"(a), "l"(b));
}

// pass1 skew: f(x) = x + (x>>4); lane base 16t -> 17t (coprime 32)
#define SK1 600   // f(551) = 585, padded

// ---------------- Pass 1: horizontal, 16 out/thread, 1 warp/row ------------
// 128 threads = 4 warps = 4 rows. Grid = 16*512/4 = 2048. Ring W1=20.
#define W1 20
__global__ void __launch_bounds__(128, 5) rf_pass1(const float2* __restrict__ in) {
    __shared__ unsigned long long s[4][SK1];
    const int warp = threadIdx.x >> 5;
    const int t    = threadIdx.x & 31;
    const int row  = blockIdx.x * 4 + warp;    // b*512 + h
    const float2* src = in + (size_t)row * IMG_W;
    unsigned long long* S = s[warp];

    // interior fill: x = 20 + t + 32j -> w = t + 32j in [0,512); MLP=16
    {
        float2 v[16];
#pragma unroll
        for (int j = 0; j < 16; ++j) v[j] = src[t + 32 * j];
#pragma unroll
        for (int j = 0; j < 16; ++j) {
            const int x = 20 + t + 32 * j;
            float vx = fmaf(v[j].x, SCALE_A, SCALE_B);
            float vy = fmaf(v[j].y, SCALE_A, SCALE_B);
            *reinterpret_cast<float2*>(&S[x + (x >> 4)]) = make_float2(vx, vy);
        }
        if (t < 20) {                          // zero edges
            S[t] = 0ull;                       // f(t)=t for t<16.. (t>>4)=1 for 16..19
            S[t + (t >> 4)] = 0ull;            // safe both
            const int x = 532 + t;
            S[x + (x >> 4)] = 0ull;
        }
    }
    __syncwarp();

    const int base = t * 17;                   // skewed base (w0 = 16t)
    unsigned long long win[W1], acc[16];
#pragma unroll
    for (int i = 0; i < W1; ++i) win[i] = S[base + i + (i >> 4)];
#pragma unroll
    for (int r = 0; r < 16; ++r) acc[r] = 0ull;

#pragma unroll
    for (int k = 0; k < 41; ++k) {
        const unsigned long long g = pk2(GK[k]);
#pragma unroll
        for (int r = 0; r < 16; ++r) ffma2(acc[r], win[(k + r) % W1], g);
        if (k < 36) {                          // prefetch i = k + 20 (max 55)
            const int i = k + W1;
            win[k % W1] = S[base + i + (i >> 4)];
        }
    }
    __syncwarp();

    // restage at f(16t+r) = 17t + r, then coalesced stores x = t + 32j
#pragma unroll
    for (int r = 0; r < 16; ++r) S[base + r] = acc[r];
    __syncwarp();

    unsigned long long* dst = g_scratch + (size_t)row * IMG_W;
#pragma unroll
    for (int j = 0; j < 16; ++j) {
        const int x = t + 32 * j;
        dst[x] = S[x + (x >> 4)];
    }
}

// ---------------- Pass 2: vertical, 16 out/thread, ring W2=24 (R9) ---------
#define W2 24
__global__ void __launch_bounds__(128, 5) rf_pass2(float2* __restrict__ out) {
    const int w  = (blockIdx.x & 3) * 128 + threadIdx.x;
    const int bh = blockIdx.x >> 2;
    const int b  = bh >> 5;
    const int h0 = (bh & 31) * 16;

    const unsigned long long* src =
        g_scratch + (size_t)b * IMG_H * IMG_W + w;

    unsigned long long win[W2], acc[16];
#pragma unroll
    for (int i = 0; i < W2; ++i) {
        const int h = h0 + i - 20;
        win[i] = ((unsigned)h < (unsigned)IMG_H) ? src[(size_t)h * IMG_W] : 0ull;
    }
#pragma unroll
    for (int r = 0; r < 16; ++r) acc[r] = 0ull;

#pragma unroll
    for (int k = 0; k < 41; ++k) {
        const unsigned long long g = pk2(GK[k]);
#pragma unroll
        for (int r = 0; r < 16; ++r) ffma2(acc[r], win[(k + r) % W2], g);
        if (k < 32) {                          // prefetch i = k + 24
            const int h = h0 + k + 4;
            win[k % W2] = ((unsigned)h < (unsigned)IMG_H) ? src[(size_t)h * IMG_W]
                                                          : 0ull;
        }
    }

    unsigned long long* dst = (unsigned long long*)out
                            + ((size_t)b * IMG_H + h0) * IMG_W + w;
#pragma unroll
    for (int r = 0; r < 16; ++r) dst[(size_t)r * IMG_W] = acc[r];
}

extern "C" void kernel_launch(void* const* d_in, const int* in_sizes, int n_in,
                              void* d_out, int out_size) {
    const float2* noise = nullptr;
    for (int i = 0; i < n_in; ++i) {
        if (in_sizes[i] == IMG_B * IMG_H * IMG_W * 2) {
            noise = (const float2*)d_in[i];
            break;
        }
    }
    if (!noise) noise = (const float2*)d_in[n_in - 1];

    rf_pass1<<<IMG_B * IMG_H / 4, 128>>>(noise);
    rf_pass2<<<IMG_B * (IMG_H / 16) * (IMG_W / 128), 128>>>((float2*)d_out);
}